// round 2
// baseline (speedup 1.0000x reference)
#include <cuda_runtime.h>
#include <cstdint>

// DCNv2 specialization for this problem instance.
// Key facts exploited:
//  - offsets depend only on (b,g,k): constant fractional shift per plane
//  - p_y,p_x in {-1,0,1}: only 3 distinct row shifts x 3 col shifts, middle = 0
//  - einsum out[16] = W[16x27] @ s[27] done with packed fma.rn.f32x2 over o-pairs

namespace {
constexpr int Hdim = 160;
constexpr int Wdim = 160;
constexpr int TILE = 32;
constexpr int HALO = 5;                 // shifts provably in [-4,4], +1 for corner
constexpr int SMW  = TILE + 2 * HALO;   // 42
constexpr int THREADS = 256;
}

typedef unsigned long long u64;

__device__ __forceinline__ u64 pack2(float x) {
    u64 r;
    asm("mov.b64 %0, {%1, %1};" : "=l"(r) : "f"(x));
    return r;
}
__device__ __forceinline__ void fma2(u64& d, u64 a, u64 b) {
    asm("fma.rn.f32x2 %0, %1, %2, %0;" : "+l"(d) : "l"(a), "l"(b));
}

// Accumulate one tap (ck = c*9+k) into all 8 output-pair accumulators.
#define EINSUM(CK, S0, S1, S2, S3) do {                                   \
    u64 sp0 = pack2(S0), sp1 = pack2(S1), sp2 = pack2(S2), sp3 = pack2(S3); \
    const u64* wr = reinterpret_cast<const u64*>(wsm[CK]);                \
    _Pragma("unroll")                                                     \
    for (int op = 0; op < 8; op++) {                                      \
        u64 w = wr[op];                                                   \
        fma2(acc[op][0], sp0, w);                                         \
        fma2(acc[op][1], sp1, w);                                         \
        fma2(acc[op][2], sp2, w);                                         \
        fma2(acc[op][3], sp3, w);                                         \
    }                                                                     \
} while (0)

__global__ __launch_bounds__(THREADS, 2)
void dcn_kernel(const float* __restrict__ input,
                const float* __restrict__ weight,
                const float* __restrict__ offset,
                float* __restrict__ out)
{
    const int bg = blockIdx.z;          // 0..47
    const int b  = bg / 3;
    const int g  = bg % 3;
    const int tile_x = blockIdx.x * TILE;
    const int tile_y = blockIdx.y * TILE;

    __shared__ float  sm[3][SMW][SMW];  // input tile + zero-padded halo
    __shared__ float2 wsm[27][8];       // [c*9+k][o_pair] = (w[2op], w[2op+1])

    const int tid = threadIdx.x;

    // ---- weights: w[g,o,c,k] = weight[k*144 + (g*16+o)*3 + c] ----
    for (int i = tid; i < 27 * 8; i += THREADS) {
        const int ck = i >> 3, op = i & 7;
        const int c = ck / 9, k = ck % 9;
        const int o0 = g * 16 + 2 * op;
        wsm[ck][op] = make_float2(weight[k * 144 + o0 * 3 + c],
                                  weight[k * 144 + (o0 + 1) * 3 + c]);
    }

    // ---- stage input tile (+halo, zero pad) ----
    const float* inb = input + (size_t)(b >> 1) * 9 * Hdim * Wdim
                             + (size_t)(g * 3) * Hdim * Wdim;
    for (int i = tid; i < 3 * SMW * SMW; i += THREADS) {
        const int c = i / (SMW * SMW);
        const int r = (i / SMW) % SMW;
        const int q = i % SMW;
        const int gy = tile_y + r - HALO;
        const int gx = tile_x + q - HALO;
        float v = 0.0f;
        if (gy >= 0 && gy < Hdim && gx >= 0 && gx < Wdim)
            v = inb[(size_t)c * Hdim * Wdim + gy * Wdim + gx];
        sm[c][r][q] = v;
    }

    // ---- shift constants (uniform across block; broadcast LDG) ----
    const float offy = __ldg(&offset[(b * 3 + g) * 2 + 0]);
    const float offx = __ldg(&offset[(b * 3 + g) * 2 + 1]);
    const float dyv = 1.0f + 3.0f / offy;   // |dy| for p_y = +-1; p_y=0 -> shift 0
    const float dxv = 1.0f + 3.0f / offx;
    const float fyMf = floorf(-dyv), fyPf = floorf(dyv);
    const float fxMf = floorf(-dxv), fxPf = floorf(dxv);
    const int fyM = (int)fyMf, fyP = (int)fyPf;
    const int fxM = (int)fxMf, fxP = (int)fxPf;
    const float wyM = -dyv - fyMf, wyP = dyv - fyPf;
    const float wxM = -dxv - fxMf, wxP = dxv - fxPf;

    __syncthreads();

    // ---- compute: thread = 1 column x 4 contiguous rows ----
    const int tx = tid & 31;
    const int r0 = (tid >> 5) * 4;

    u64 acc[8][4];
    #pragma unroll
    for (int op = 0; op < 8; op++)
        #pragma unroll
        for (int p = 0; p < 4; p++)
            acc[op][p] = 0ull;

    #pragma unroll 1
    for (int c = 0; c < 3; c++) {
        const float* B  = &sm[c][r0 + HALO][tx + HALO];
        const float* BM = B + fyM * SMW;    // rows for p_y = -1
        const float* BP = B + fyP * SMW;    // rows for p_y = +1
        const int ckb = c * 9;

        // ===== p_y = 0 (no vertical interp): rows B[p*SMW] =====
        {   // k=4: center tap, direct loads
            EINSUM(ckb + 4, B[0], B[SMW], B[2 * SMW], B[3 * SMW]);
        }
        {   // k=3: horizontal lerp at fxM
            float t[4];
            #pragma unroll
            for (int p = 0; p < 4; p++) {
                float a = B[p * SMW + fxM], bb = B[p * SMW + fxM + 1];
                t[p] = fmaf(wxM, bb - a, a);
            }
            EINSUM(ckb + 3, t[0], t[1], t[2], t[3]);
        }
        {   // k=5: horizontal lerp at fxP
            float t[4];
            #pragma unroll
            for (int p = 0; p < 4; p++) {
                float a = B[p * SMW + fxP], bb = B[p * SMW + fxP + 1];
                t[p] = fmaf(wxP, bb - a, a);
            }
            EINSUM(ckb + 5, t[0], t[1], t[2], t[3]);
        }

        // ===== p_y = -1 (rows BM, weight wyM) =====
        {   // k=1: vertical-only lerp, column 0
            float v[5];
            #pragma unroll
            for (int j = 0; j < 5; j++) v[j] = BM[j * SMW];
            float t[4];
            #pragma unroll
            for (int p = 0; p < 4; p++) t[p] = fmaf(wyM, v[p + 1] - v[p], v[p]);
            EINSUM(ckb + 1, t[0], t[1], t[2], t[3]);
        }
        {   // k=0: full bilinear, cols fxM (horizontal-first shares 5 row-lerps)
            float h[5];
            #pragma unroll
            for (int j = 0; j < 5; j++) {
                float a = BM[j * SMW + fxM], bb = BM[j * SMW + fxM + 1];
                h[j] = fmaf(wxM, bb - a, a);
            }
            float t[4];
            #pragma unroll
            for (int p = 0; p < 4; p++) t[p] = fmaf(wyM, h[p + 1] - h[p], h[p]);
            EINSUM(ckb + 0, t[0], t[1], t[2], t[3]);
        }
        {   // k=2: full bilinear, cols fxP
            float h[5];
            #pragma unroll
            for (int j = 0; j < 5; j++) {
                float a = BM[j * SMW + fxP], bb = BM[j * SMW + fxP + 1];
                h[j] = fmaf(wxP, bb - a, a);
            }
            float t[4];
            #pragma unroll
            for (int p = 0; p < 4; p++) t[p] = fmaf(wyM, h[p + 1] - h[p], h[p]);
            EINSUM(ckb + 2, t[0], t[1], t[2], t[3]);
        }

        // ===== p_y = +1 (rows BP, weight wyP) =====
        {   // k=7: vertical-only lerp
            float v[5];
            #pragma unroll
            for (int j = 0; j < 5; j++) v[j] = BP[j * SMW];
            float t[4];
            #pragma unroll
            for (int p = 0; p < 4; p++) t[p] = fmaf(wyP, v[p + 1] - v[p], v[p]);
            EINSUM(ckb + 7, t[0], t[1], t[2], t[3]);
        }
        {   // k=6: full bilinear, cols fxM
            float h[5];
            #pragma unroll
            for (int j = 0; j < 5; j++) {
                float a = BP[j * SMW + fxM], bb = BP[j * SMW + fxM + 1];
                h[j] = fmaf(wxM, bb - a, a);
            }
            float t[4];
            #pragma unroll
            for (int p = 0; p < 4; p++) t[p] = fmaf(wyP, h[p + 1] - h[p], h[p]);
            EINSUM(ckb + 6, t[0], t[1], t[2], t[3]);
        }
        {   // k=8: full bilinear, cols fxP
            float h[5];
            #pragma unroll
            for (int j = 0; j < 5; j++) {
                float a = BP[j * SMW + fxP], bb = BP[j * SMW + fxP + 1];
                h[j] = fmaf(wxP, bb - a, a);
            }
            float t[4];
            #pragma unroll
            for (int p = 0; p < 4; p++) t[p] = fmaf(wyP, h[p + 1] - h[p], h[p]);
            EINSUM(ckb + 8, t[0], t[1], t[2], t[3]);
        }
    }

    // ---- store: out[b][g*16 + 2*op(+1)][y][x] ----
    float* outp = out + (size_t)(b * 48 + g * 16) * Hdim * Wdim
                      + (size_t)(tile_y + r0) * Wdim + tile_x + tx;
    #pragma unroll
    for (int op = 0; op < 8; op++) {
        #pragma unroll
        for (int p = 0; p < 4; p++) {
            float lo, hi;
            asm("mov.b64 {%0, %1}, %2;" : "=f"(lo), "=f"(hi) : "l"(acc[op][p]));
            outp[(size_t)(2 * op)     * (Hdim * Wdim) + p * Wdim] = lo;
            outp[(size_t)(2 * op + 1) * (Hdim * Wdim) + p * Wdim] = hi;
        }
    }
}

extern "C" void kernel_launch(void* const* d_in, const int* in_sizes, int n_in,
                              void* d_out, int out_size)
{
    const float* input  = (const float*)d_in[0];
    const float* weight = (const float*)d_in[1];
    const float* offset = (const float*)d_in[2];
    float* out = (float*)d_out;

    dim3 grid(Wdim / TILE, Hdim / TILE, 48);   // 5 x 5 x 48
    dcn_kernel<<<grid, THREADS>>>(input, weight, offset, out);
}

// round 3
// speedup vs baseline: 1.2958x; 1.2958x over previous
#include <cuda_runtime.h>
#include <cstdint>

// DCNv2 specialization (R3):
//  - offsets depend only on (b,g,k): constant fractional shift per plane
//  - p in {-1,0,1}: center tap = direct load; edge taps = 1-D lerp;
//    corner taps = bilinear with horizontal row-lerps shared over 4 rows
//  - scalar FFMA einsum (R2's f32x2 regressed: RF-banking rt=3 + asm blocked
//    scheduling); weights staged [tap][16] and loaded as float4 (LDS.128)

namespace {
constexpr int Hdim = 160;
constexpr int Wdim = 160;
constexpr int TILE = 32;
constexpr int HALO = 5;                 // shifts provably in [-4,4], +1 corner
constexpr int SMW  = TILE + 2 * HALO;   // 42
constexpr int THREADS = 256;
}

// Accumulate tap CK's 4 pixel samples into all 16 output accumulators.
#define EINSUM(CK, S0, S1, S2, S3) do {                                     \
    const float4* wr = reinterpret_cast<const float4*>(wsm[CK]);            \
    _Pragma("unroll")                                                       \
    for (int q = 0; q < 4; q++) {                                           \
        const float4 w = wr[q];                                             \
        acc[4*q+0][0] = fmaf(S0, w.x, acc[4*q+0][0]);                       \
        acc[4*q+0][1] = fmaf(S1, w.x, acc[4*q+0][1]);                       \
        acc[4*q+0][2] = fmaf(S2, w.x, acc[4*q+0][2]);                       \
        acc[4*q+0][3] = fmaf(S3, w.x, acc[4*q+0][3]);                       \
        acc[4*q+1][0] = fmaf(S0, w.y, acc[4*q+1][0]);                       \
        acc[4*q+1][1] = fmaf(S1, w.y, acc[4*q+1][1]);                       \
        acc[4*q+1][2] = fmaf(S2, w.y, acc[4*q+1][2]);                       \
        acc[4*q+1][3] = fmaf(S3, w.y, acc[4*q+1][3]);                       \
        acc[4*q+2][0] = fmaf(S0, w.z, acc[4*q+2][0]);                       \
        acc[4*q+2][1] = fmaf(S1, w.z, acc[4*q+2][1]);                       \
        acc[4*q+2][2] = fmaf(S2, w.z, acc[4*q+2][2]);                       \
        acc[4*q+2][3] = fmaf(S3, w.z, acc[4*q+2][3]);                       \
        acc[4*q+3][0] = fmaf(S0, w.w, acc[4*q+3][0]);                       \
        acc[4*q+3][1] = fmaf(S1, w.w, acc[4*q+3][1]);                       \
        acc[4*q+3][2] = fmaf(S2, w.w, acc[4*q+3][2]);                       \
        acc[4*q+3][3] = fmaf(S3, w.w, acc[4*q+3][3]);                       \
    }                                                                       \
} while (0)

__global__ __launch_bounds__(THREADS, 2)
void dcn_kernel(const float* __restrict__ input,
                const float* __restrict__ weight,
                const float* __restrict__ offset,
                float* __restrict__ out)
{
    const int bg = blockIdx.z;          // 0..47
    const int b  = bg / 3;
    const int g  = bg % 3;
    const int tile_x = blockIdx.x * TILE;
    const int tile_y = blockIdx.y * TILE;

    __shared__ float sm[3][SMW][SMW];               // input tile + halo
    __shared__ __align__(16) float wsm[27][16];     // [c*9+k][o]

    const int tid = threadIdx.x;

    // ---- weights: w[g,o,c,k] = weight[k*144 + (g*16+o)*3 + c] ----
    for (int i = tid; i < 27 * 16; i += THREADS) {
        const int ck = i >> 4, o = i & 15;
        const int c = ck / 9, k = ck % 9;
        wsm[ck][o] = weight[k * 144 + (g * 16 + o) * 3 + c];
    }

    // ---- stage input tile (+halo, zero pad) ----
    const float* inb = input + (size_t)(b >> 1) * 9 * Hdim * Wdim
                             + (size_t)(g * 3) * Hdim * Wdim;
    for (int i = tid; i < 3 * SMW * SMW; i += THREADS) {
        const int c = i / (SMW * SMW);
        const int r = (i / SMW) % SMW;
        const int q = i % SMW;
        const int gy = tile_y + r - HALO;
        const int gx = tile_x + q - HALO;
        float v = 0.0f;
        if (gy >= 0 && gy < Hdim && gx >= 0 && gx < Wdim)
            v = inb[(size_t)c * Hdim * Wdim + gy * Wdim + gx];
        sm[c][r][q] = v;
    }

    // ---- shift constants (uniform across block) ----
    const float offy = __ldg(&offset[(b * 3 + g) * 2 + 0]);
    const float offx = __ldg(&offset[(b * 3 + g) * 2 + 1]);
    const float dyv = 1.0f + 3.0f / offy;   // shift magnitude for p_y = +-1
    const float dxv = 1.0f + 3.0f / offx;
    const float fyMf = floorf(-dyv), fyPf = floorf(dyv);
    const float fxMf = floorf(-dxv), fxPf = floorf(dxv);
    const int fyM = (int)fyMf, fyP = (int)fyPf;
    const int fxM = (int)fxMf, fxP = (int)fxPf;
    const float wyM = -dyv - fyMf, wyP = dyv - fyPf;
    const float wxM = -dxv - fxMf, wxP = dxv - fxPf;

    __syncthreads();

    // ---- compute: thread = 1 column x 4 contiguous rows ----
    const int tx = tid & 31;
    const int r0 = (tid >> 5) * 4;

    float acc[16][4];
    #pragma unroll
    for (int o = 0; o < 16; o++)
        #pragma unroll
        for (int p = 0; p < 4; p++)
            acc[o][p] = 0.0f;

    #pragma unroll 1
    for (int c = 0; c < 3; c++) {
        const float* B  = &sm[c][r0 + HALO][tx + HALO];
        const float* BM = B + fyM * SMW;    // rows for p_y = -1
        const float* BP = B + fyP * SMW;    // rows for p_y = +1
        const int ckb = c * 9;

        // ===== p_y = 0 =====
        {   // k=4: center tap, direct loads
            EINSUM(ckb + 4, B[0], B[SMW], B[2 * SMW], B[3 * SMW]);
        }
        {   // k=3: horizontal lerp at fxM
            float t[4];
            #pragma unroll
            for (int p = 0; p < 4; p++) {
                float a = B[p * SMW + fxM], bb = B[p * SMW + fxM + 1];
                t[p] = fmaf(wxM, bb - a, a);
            }
            EINSUM(ckb + 3, t[0], t[1], t[2], t[3]);
        }
        {   // k=5: horizontal lerp at fxP
            float t[4];
            #pragma unroll
            for (int p = 0; p < 4; p++) {
                float a = B[p * SMW + fxP], bb = B[p * SMW + fxP + 1];
                t[p] = fmaf(wxP, bb - a, a);
            }
            EINSUM(ckb + 5, t[0], t[1], t[2], t[3]);
        }

        // ===== p_y = -1 (rows BM, weight wyM) =====
        {   // k=1: vertical-only lerp (col 0), 5 loads for 4 pixels
            float v[5];
            #pragma unroll
            for (int j = 0; j < 5; j++) v[j] = BM[j * SMW];
            float t[4];
            #pragma unroll
            for (int p = 0; p < 4; p++) t[p] = fmaf(wyM, v[p + 1] - v[p], v[p]);
            EINSUM(ckb + 1, t[0], t[1], t[2], t[3]);
        }
        {   // k=0: bilinear; 5 shared horizontal lerps at fxM
            float h[5];
            #pragma unroll
            for (int j = 0; j < 5; j++) {
                float a = BM[j * SMW + fxM], bb = BM[j * SMW + fxM + 1];
                h[j] = fmaf(wxM, bb - a, a);
            }
            float t[4];
            #pragma unroll
            for (int p = 0; p < 4; p++) t[p] = fmaf(wyM, h[p + 1] - h[p], h[p]);
            EINSUM(ckb + 0, t[0], t[1], t[2], t[3]);
        }
        {   // k=2: bilinear at fxP
            float h[5];
            #pragma unroll
            for (int j = 0; j < 5; j++) {
                float a = BM[j * SMW + fxP], bb = BM[j * SMW + fxP + 1];
                h[j] = fmaf(wxP, bb - a, a);
            }
            float t[4];
            #pragma unroll
            for (int p = 0; p < 4; p++) t[p] = fmaf(wyM, h[p + 1] - h[p], h[p]);
            EINSUM(ckb + 2, t[0], t[1], t[2], t[3]);
        }

        // ===== p_y = +1 (rows BP, weight wyP) =====
        {   // k=7: vertical-only lerp
            float v[5];
            #pragma unroll
            for (int j = 0; j < 5; j++) v[j] = BP[j * SMW];
            float t[4];
            #pragma unroll
            for (int p = 0; p < 4; p++) t[p] = fmaf(wyP, v[p + 1] - v[p], v[p]);
            EINSUM(ckb + 7, t[0], t[1], t[2], t[3]);
        }
        {   // k=6: bilinear at fxM
            float h[5];
            #pragma unroll
            for (int j = 0; j < 5; j++) {
                float a = BP[j * SMW + fxM], bb = BP[j * SMW + fxM + 1];
                h[j] = fmaf(wxM, bb - a, a);
            }
            float t[4];
            #pragma unroll
            for (int p = 0; p < 4; p++) t[p] = fmaf(wyP, h[p + 1] - h[p], h[p]);
            EINSUM(ckb + 6, t[0], t[1], t[2], t[3]);
        }
        {   // k=8: bilinear at fxP
            float h[5];
            #pragma unroll
            for (int j = 0; j < 5; j++) {
                float a = BP[j * SMW + fxP], bb = BP[j * SMW + fxP + 1];
                h[j] = fmaf(wxP, bb - a, a);
            }
            float t[4];
            #pragma unroll
            for (int p = 0; p < 4; p++) t[p] = fmaf(wyP, h[p + 1] - h[p], h[p]);
            EINSUM(ckb + 8, t[0], t[1], t[2], t[3]);
        }
    }

    // ---- store: out[b][g*16+o][y][x] ----
    float* outp = out + (size_t)(b * 48 + g * 16) * Hdim * Wdim
                      + (size_t)(tile_y + r0) * Wdim + tile_x + tx;
    #pragma unroll
    for (int o = 0; o < 16; o++) {
        #pragma unroll
        for (int p = 0; p < 4; p++)
            outp[(size_t)o * (Hdim * Wdim) + p * Wdim] = acc[o][p];
    }
}

extern "C" void kernel_launch(void* const* d_in, const int* in_sizes, int n_in,
                              void* d_out, int out_size)
{
    const float* input  = (const float*)d_in[0];
    const float* weight = (const float*)d_in[1];
    const float* offset = (const float*)d_in[2];
    float* out = (float*)d_out;

    dim3 grid(Wdim / TILE, Hdim / TILE, 48);   // 5 x 5 x 48
    dcn_kernel<<<grid, THREADS>>>(input, weight, offset, out);
}